// round 5
// baseline (speedup 1.0000x reference)
#include <cuda_runtime.h>

#define F_DIM   128
#define NRBF    20
#define IN_DIM  276          // 2F + NRBF
#define LDA0    280          // padded h0 row (multiple of 8, covers k-overrun)
#define TILE    64           // edges per block
#define NTHREADS 256

// edge_index dtype mode: 1 = int64 (long long), 0 = int32. Written by the
// sniffer kernel, consumed by the edge kernel (same stream => ordered).
__device__ int g_ei_mode;

__device__ __forceinline__ float silu_f(float x) {
    return x / (1.0f + __expf(-x));
}

// Detect whether the edge-index buffer is int64 or int32 by range-checking the
// first 64 entries under the int64 interpretation. int64-of-int32 data pairs
// two int32 words => values ~2^32+ => out of [0,Nn) => mode32. Deterministic.
__global__ void detect_ei_kernel(const void* __restrict__ ei, long long Ee, int Nn) {
    const long long* p64 = (const long long*)ei;
    int ok = 1;
    long long ns = (Ee < 64) ? Ee : 64;
    for (long long i = 0; i < ns; i++) {
        long long a = p64[i];
        if (a < 0 || a >= (long long)Nn) { ok = 0; break; }
    }
    g_ei_mode = ok;
}

// Register-tiled GEMM: C[64 x 256] = A[64 x K] @ W[K x 256]
// thread (tx in [0,64), ty in [0,4)) owns rows {ty, ty+4, ..., ty+60} x cols [4tx, 4tx+4)
// W is staged through shared in 8-row slices (zero-padded on the K remainder,
// so the inner loop is always a full unrolled 8).
template<int K, bool SPLIT>
__device__ __forceinline__ void gemm_acc(
    const float* __restrict__ A, int lda,
    const float* __restrict__ Wa, const float* __restrict__ Wb,
    float* __restrict__ wst, float acc[16][4], int tx, int ty, int tid)
{
#pragma unroll
    for (int i = 0; i < 16; i++)
#pragma unroll
        for (int j = 0; j < 4; j++) acc[i][j] = 0.0f;

    for (int k0 = 0; k0 < K; k0 += 8) {
        int kc = K - k0; if (kc > 8) kc = 8;
        __syncthreads();   // previous consumers of wst are done
#pragma unroll
        for (int t = 0; t < 8; t++) {
            int idx = tid + t * NTHREADS;      // 2048 = 8*256 elements
            int r = idx >> 8;
            int c = idx & 255;
            float w = 0.0f;
            if (r < kc) {
                if (!SPLIT) {
                    w = Wa[(k0 + r) * 256 + c];
                } else {
                    w = (c < 128) ? Wa[(k0 + r) * 128 + c]
                                  : Wb[(k0 + r) * 128 + (c - 128)];
                }
            }
            wst[idx] = w;
        }
        __syncthreads();
        const float* Arow = A + ty * lda + k0;
#pragma unroll
        for (int kk = 0; kk < 8; kk++) {
            float4 b4 = *(const float4*)(wst + kk * 256 + tx * 4);
#pragma unroll
            for (int i = 0; i < 16; i++) {
                float a = Arow[4 * i * lda + kk];   // broadcast within warp (one ty/warp)
                acc[i][0] = fmaf(a, b4.x, acc[i][0]);
                acc[i][1] = fmaf(a, b4.y, acc[i][1]);
                acc[i][2] = fmaf(a, b4.z, acc[i][2]);
                acc[i][3] = fmaf(a, b4.w, acc[i][3]);
            }
        }
    }
}

__global__ __launch_bounds__(NTHREADS, 1)
void painn_edge_kernel(
    const float* __restrict__ s, const float* __restrict__ pos,
    const void* __restrict__ ei_raw,
    const float* __restrict__ W1, const float* __restrict__ b1,
    const float* __restrict__ W2, const float* __restrict__ b2,
    const float* __restrict__ Ws, const float* __restrict__ bs,
    const float* __restrict__ Wv, const float* __restrict__ bv,
    const float* __restrict__ centers, const float* __restrict__ widths,
    float* __restrict__ out, int Nn, long long Ee)
{
    extern __shared__ float smem[];
    float* h0    = smem;                      // 64*280
    float* h1    = h0 + TILE * LDA0;          // 64*256
    float* wst   = h1 + TILE * 256;           // 8*256
    float* dirs  = wst + 8 * 256;             // 64*4
    float* dists = dirs + TILE * 4;           // 64
    int*   srcsh = (int*)(dists + TILE);      // 64
    int*   dstsh = srcsh + TILE;              // 64

    const int tid = threadIdx.x;
    const int tx  = tid & 63;
    const int ty  = tid >> 6;
    const long long e0 = (long long)blockIdx.x * TILE;

    // ---- phase 1: per-edge geometry ----
    if (tid < TILE) {
        long long e = e0 + tid;
        int srci = 0, dsti = 0;
        float dx = 0.f, dy = 0.f, dz = 0.f, dd = 0.f, inv = 0.f;
        if (e < Ee) {
            long long a, b;
            if (g_ei_mode) {
                const long long* p64 = (const long long*)ei_raw;
                a = p64[e];
                b = p64[Ee + e];
            } else {
                const int* p32 = (const int*)ei_raw;
                a = p32[e];
                b = p32[Ee + e];
            }
            // defensive clamp: no interpretation of the input may ever produce
            // an out-of-range pointer (wild generic atomics trap with err 717)
            srci = (int)a; if (srci < 0) srci = 0; if (srci >= Nn) srci = Nn - 1;
            dsti = (int)b; if (dsti < 0) dsti = 0; if (dsti >= Nn) dsti = Nn - 1;
            dx = pos[dsti * 3 + 0] - pos[srci * 3 + 0];
            dy = pos[dsti * 3 + 1] - pos[srci * 3 + 1];
            dz = pos[dsti * 3 + 2] - pos[srci * 3 + 2];
            dd = sqrtf(dx * dx + dy * dy + dz * dz);
            inv = (dd > 0.f) ? 1.0f / dd : 0.0f;
        }
        srcsh[tid] = srci;
        dstsh[tid] = dsti;
        dirs[tid * 4 + 0] = dx * inv;
        dirs[tid * 4 + 1] = dy * inv;
        dirs[tid * 4 + 2] = dz * inv;
        dists[tid] = dd;
    }
    __syncthreads();

    // ---- phase 2: build h0 = [s[src] | s[dst] | rbf | 0-pad] ----
    for (int idx = tid; idx < TILE * LDA0; idx += NTHREADS) {
        int r = idx / LDA0;
        int c = idx - r * LDA0;
        float val = 0.0f;
        if (e0 + r < Ee) {
            if (c < F_DIM) {
                val = s[(size_t)srcsh[r] * F_DIM + c];
            } else if (c < 2 * F_DIM) {
                val = s[(size_t)dstsh[r] * F_DIM + (c - F_DIM)];
            } else if (c < IN_DIM) {
                int k = c - 2 * F_DIM;
                float t = (dists[r] - centers[k]) / (widths[k] + 1e-8f);
                val = __expf(-t * t);
            }
        }
        h0[idx] = val;
    }

    float acc[16][4];

    // ---- GEMM1: h1 = silu(h0 @ W1 + b1) ----
    gemm_acc<IN_DIM, false>(h0, LDA0, W1, W1, wst, acc, tx, ty, tid);
    {
        float4 bb = *(const float4*)(b1 + tx * 4);
#pragma unroll
        for (int i = 0; i < 16; i++) {
            int r = ty + 4 * i;
            float4 o;
            o.x = silu_f(acc[i][0] + bb.x);
            o.y = silu_f(acc[i][1] + bb.y);
            o.z = silu_f(acc[i][2] + bb.z);
            o.w = silu_f(acc[i][3] + bb.w);
            *(float4*)(h1 + r * 256 + tx * 4) = o;
        }
    }

    // ---- GEMM2: h2 = silu(h1 @ W2 + b2), written into h0's buffer (stride 256) ----
    gemm_acc<256, false>(h1, 256, W2, W2, wst, acc, tx, ty, tid);
    {
        float4 bb = *(const float4*)(b2 + tx * 4);
#pragma unroll
        for (int i = 0; i < 16; i++) {
            int r = ty + 4 * i;
            float4 o;
            o.x = silu_f(acc[i][0] + bb.x);
            o.y = silu_f(acc[i][1] + bb.y);
            o.z = silu_f(acc[i][2] + bb.z);
            o.w = silu_f(acc[i][3] + bb.w);
            *(float4*)(h0 + r * 256 + tx * 4) = o;
        }
    }

    // ---- GEMM3: [ds | dv_mag] = h2 @ [Ws | Wv], then scatter ----
    gemm_acc<256, true>(h0, 256, Ws, Wv, wst, acc, tx, ty, tid);
    {
        const float* bp = (tx < 32) ? (bs + tx * 4) : (bv + (tx * 4 - 128));
        float4 bb = *(const float4*)bp;
        const size_t NF = (size_t)Nn * F_DIM;
#pragma unroll 4
        for (int i = 0; i < 16; i++) {
            int r = ty + 4 * i;
            if (e0 + r >= Ee) break;     // rows monotonic in i
            int d = dstsh[r];
            if (tx < 32) {
                float* o = out + (size_t)d * F_DIM + tx * 4;
                atomicAdd(o + 0, acc[i][0] + bb.x);
                atomicAdd(o + 1, acc[i][1] + bb.y);
                atomicAdd(o + 2, acc[i][2] + bb.z);
                atomicAdd(o + 3, acc[i][3] + bb.w);
            } else {
                float ddx = dirs[r * 4 + 0];
                float ddy = dirs[r * 4 + 1];
                float ddz = dirs[r * 4 + 2];
                float m0 = acc[i][0] + bb.x;
                float m1 = acc[i][1] + bb.y;
                float m2 = acc[i][2] + bb.z;
                float m3 = acc[i][3] + bb.w;
                float* o = out + NF + (size_t)d * 3 * F_DIM + (tx * 4 - 128);
                atomicAdd(o + 0,             ddx * m0);
                atomicAdd(o + 1,             ddx * m1);
                atomicAdd(o + 2,             ddx * m2);
                atomicAdd(o + 3,             ddx * m3);
                atomicAdd(o + F_DIM + 0,     ddy * m0);
                atomicAdd(o + F_DIM + 1,     ddy * m1);
                atomicAdd(o + F_DIM + 2,     ddy * m2);
                atomicAdd(o + F_DIM + 3,     ddy * m3);
                atomicAdd(o + 2 * F_DIM + 0, ddz * m0);
                atomicAdd(o + 2 * F_DIM + 1, ddz * m1);
                atomicAdd(o + 2 * F_DIM + 2, ddz * m2);
                atomicAdd(o + 2 * F_DIM + 3, ddz * m3);
            }
        }
    }
}

// out[0:N*F] = s ; out[N*F:] = v   (both float32, layouts match)
__global__ void painn_init_kernel(float4* __restrict__ out,
                                  const float4* __restrict__ s,
                                  const float4* __restrict__ v,
                                  size_t nf4, size_t tot4)
{
    size_t i = (size_t)blockIdx.x * blockDim.x + threadIdx.x;
    if (i >= tot4) return;
    out[i] = (i < nf4) ? s[i] : v[i - nf4];
}

extern "C" void kernel_launch(void* const* d_in, const int* in_sizes, int n_in,
                              void* d_out, int out_size)
{
    const float* s       = (const float*)d_in[0];
    const float* v       = (const float*)d_in[1];
    const float* pos     = (const float*)d_in[2];
    const void*  ei      = (const void*)d_in[3];
    const float* W1      = (const float*)d_in[4];
    const float* b1      = (const float*)d_in[5];
    const float* W2      = (const float*)d_in[6];
    const float* b2      = (const float*)d_in[7];
    const float* Ws      = (const float*)d_in[8];
    const float* bs      = (const float*)d_in[9];
    const float* Wv      = (const float*)d_in[10];
    const float* bv      = (const float*)d_in[11];
    const float* centers = (const float*)d_in[12];
    const float* widths  = (const float*)d_in[13];
    float* out = (float*)d_out;

    const int       Nn = in_sizes[0] / F_DIM;
    const long long Ee = in_sizes[3] / 2;

    // sniff edge_index dtype (int64 vs int32) — deterministic, graph-capturable
    detect_ei_kernel<<<1, 1>>>(ei, Ee, Nn);

    // init: copy s and v into out
    size_t nf4  = (size_t)Nn * F_DIM / 4;
    size_t tot4 = (size_t)Nn * F_DIM;    // (F + 3F) floats / 4 = N*F float4s total
    int init_blocks = (int)((tot4 + 255) / 256);
    painn_init_kernel<<<init_blocks, 256>>>((float4*)out, (const float4*)s,
                                            (const float4*)v, nf4, tot4);

    // fused edge kernel
    size_t smem_bytes =
        (size_t)(TILE * LDA0 + TILE * 256 + 8 * 256 + TILE * 4 + TILE) * sizeof(float)
        + 2 * TILE * sizeof(int);
    cudaFuncSetAttribute(painn_edge_kernel,
                         cudaFuncAttributeMaxDynamicSharedMemorySize,
                         (int)smem_bytes);
    int blocks = (int)((Ee + TILE - 1) / TILE);
    painn_edge_kernel<<<blocks, NTHREADS, smem_bytes>>>(
        s, pos, ei, W1, b1, W2, b2, Ws, bs, Wv, bv, centers, widths,
        out, Nn, Ee);
}

// round 8
// speedup vs baseline: 4.7798x; 4.7798x over previous
#include <cuda_runtime.h>

#define F_DIM    128
#define NRBF     20
#define IN_DIM   276           // 2F + NRBF
#define TILE     64            // edges per block
#define NTHREADS 256
#define LD0      284           // h0 leading dim (284 % 32 == 28 -> conflict-free A reads)
#define LD1      260           // h1/h2 leading dim (260 % 32 == 4 -> conflict-free)
#define NK1      35            // ceil(280/8) k-steps, GEMM1 (K padded 276->280)
#define NK2      32            // GEMM2 K=256
#define NK3      32            // GEMM3 K=256
#define PACK_PER_KS 2048       // 32 n-tiles * 32 lanes * 2 floats

// edge_index dtype mode: 1 = int64, 0 = int32 (sniffed at runtime)
__device__ int g_ei_mode;
// fragment-packed tf32 weights: [gemm][ks][nt][lane][2]
__device__ float g_wpack[(NK1 + NK2 + NK3) * PACK_PER_KS];

__device__ __forceinline__ unsigned f2tf(float x) {
    unsigned u; asm("cvt.rna.tf32.f32 %0, %1;" : "=r"(u) : "f"(x)); return u;
}
__device__ __forceinline__ float silu_f(float x) { return x / (1.0f + __expf(-x)); }

__device__ __forceinline__ void mma_tf32(float c[4], const unsigned a[4], const unsigned b[2]) {
    asm volatile(
        "mma.sync.aligned.m16n8k8.row.col.f32.tf32.tf32.f32 "
        "{%0,%1,%2,%3}, {%4,%5,%6,%7}, {%8,%9}, {%0,%1,%2,%3};"
        : "+f"(c[0]), "+f"(c[1]), "+f"(c[2]), "+f"(c[3])
        : "r"(a[0]), "r"(a[1]), "r"(a[2]), "r"(a[3]), "r"(b[0]), "r"(b[1]));
}
__device__ __forceinline__ void red2(float* p, float x, float y) {
    asm volatile("red.global.add.v2.f32 [%0], {%1,%2};"
                 :: "l"(p), "f"(x), "f"(y) : "memory");
}

// ---------------- dtype sniffer (unchanged from passing round) ----------------
__global__ void detect_ei_kernel(const void* __restrict__ ei, long long Ee, int Nn) {
    const long long* p64 = (const long long*)ei;
    int ok = 1;
    long long ns = (Ee < 64) ? Ee : 64;
    for (long long i = 0; i < ns; i++) {
        long long a = p64[i];
        if (a < 0 || a >= (long long)Nn) { ok = 0; break; }
    }
    g_ei_mode = ok;
}

// ---------------- weight fragment packer (runs every launch; tiny) ------------
// pack[gks][nt][lane][j] = tf32(W[8*ks + (lane&3) + 4j][8*nt + (lane>>2)])
__global__ void pack_weights_kernel(const float* __restrict__ W1,
                                    const float* __restrict__ W2,
                                    const float* __restrict__ Ws,
                                    const float* __restrict__ Wv)
{
    int idx = blockIdx.x * blockDim.x + threadIdx.x;
    const int TOT = (NK1 + NK2 + NK3) * PACK_PER_KS;
    if (idx >= TOT) return;
    int j    = idx & 1;
    int lane = (idx >> 1) & 31;
    int nt   = (idx >> 6) & 31;
    int gks  = idx >> 11;
    int g = lane >> 2, t = lane & 3;
    int col = nt * 8 + g;
    int kk  = t + 4 * j;
    float val = 0.0f;
    if (gks < NK1) {
        int k = gks * 8 + kk;
        if (k < IN_DIM) val = W1[k * 256 + col];
    } else if (gks < NK1 + NK2) {
        int k = (gks - NK1) * 8 + kk;
        val = W2[k * 256 + col];
    } else {
        int k = (gks - NK1 - NK2) * 8 + kk;
        val = (col < 128) ? Ws[k * 128 + col] : Wv[k * 128 + (col - 128)];
    }
    g_wpack[idx] = __uint_as_float(f2tf(val));
}

// ---------------- warp-tiled tf32 GEMM: C[64x256] = A[64xK] @ Wpack -----------
// warp tile: 32 rows x 64 cols; A from smem (scalar LDS, conflict-free),
// B fragments direct LDG.64 from packed global; double-buffered, fully unrolled.
template<int NK>
__device__ __forceinline__ void gemm_mma(const float* __restrict__ Asm, int LD,
                                         const float* __restrict__ Wg,
                                         float (&c)[2][8][4],
                                         int g, int t, int lane,
                                         int warp_m, int warp_n)
{
#pragma unroll
    for (int mt = 0; mt < 2; mt++)
#pragma unroll
        for (int nt = 0; nt < 8; nt++)
#pragma unroll
            for (int q = 0; q < 4; q++) c[mt][nt][q] = 0.0f;

    const float2* wp  = (const float2*)Wg + warp_n * 8 * 32 + lane;
    const float*  a0p = Asm + (warp_m * 32 + g) * LD + t;

    unsigned a[2][2][4];
    unsigned b[2][8][2];

#pragma unroll
    for (int nt = 0; nt < 8; nt++) {
        float2 v = __ldg(wp + nt * 32);
        b[0][nt][0] = __float_as_uint(v.x);
        b[0][nt][1] = __float_as_uint(v.y);
    }
#pragma unroll
    for (int mt = 0; mt < 2; mt++) {
        const float* p = a0p + mt * 16 * LD;
        a[0][mt][0] = __float_as_uint(p[0]);
        a[0][mt][1] = __float_as_uint(p[8 * LD]);
        a[0][mt][2] = __float_as_uint(p[4]);
        a[0][mt][3] = __float_as_uint(p[8 * LD + 4]);
    }

#pragma unroll
    for (int ks = 0; ks < NK; ks++) {
        const int cur = ks & 1, nxt = cur ^ 1;
        if (ks + 1 < NK) {
            const float2* wq = wp + (ks + 1) * 1024;
#pragma unroll
            for (int nt = 0; nt < 8; nt++) {
                float2 v = __ldg(wq + nt * 32);
                b[nxt][nt][0] = __float_as_uint(v.x);
                b[nxt][nt][1] = __float_as_uint(v.y);
            }
            const float* ap = a0p + (ks + 1) * 8;
#pragma unroll
            for (int mt = 0; mt < 2; mt++) {
                const float* p = ap + mt * 16 * LD;
                a[nxt][mt][0] = __float_as_uint(p[0]);
                a[nxt][mt][1] = __float_as_uint(p[8 * LD]);
                a[nxt][mt][2] = __float_as_uint(p[4]);
                a[nxt][mt][3] = __float_as_uint(p[8 * LD + 4]);
            }
        }
#pragma unroll
        for (int mt = 0; mt < 2; mt++)
#pragma unroll
            for (int nt = 0; nt < 8; nt++)
                mma_tf32(c[mt][nt], a[cur][mt], b[cur][nt]);
    }
}

__global__ __launch_bounds__(NTHREADS, 1)
void painn_mma_kernel(
    const float* __restrict__ s, const float* __restrict__ pos,
    const void* __restrict__ ei_raw,
    const float* __restrict__ b1, const float* __restrict__ b2,
    const float* __restrict__ bs, const float* __restrict__ bv,
    const float* __restrict__ centers, const float* __restrict__ widths,
    float* __restrict__ out, int Nn, long long Ee)
{
    extern __shared__ float smem[];
    float* h0    = smem;                     // 64*284
    float* h1    = h0 + TILE * LD0;          // 64*260
    float* dirs  = h1 + TILE * LD1;          // 64*4
    float* dists = dirs + TILE * 4;          // 64
    int*   srcsh = (int*)(dists + TILE);     // 64
    int*   dstsh = srcsh + TILE;             // 64

    const int tid  = threadIdx.x;
    const int lane = tid & 31;
    const int wid  = tid >> 5;
    const int g = lane >> 2, t = lane & 3;
    const int warp_n = wid & 3;      // 4 groups of 64 cols
    const int warp_m = wid >> 2;     // 2 groups of 32 rows
    const long long e0 = (long long)blockIdx.x * TILE;

    // ---- phase 1: per-edge geometry ----
    if (tid < TILE) {
        long long e = e0 + tid;
        int srci = 0, dsti = 0;
        float dx = 0.f, dy = 0.f, dz = 0.f, dd = 0.f, inv = 0.f;
        if (e < Ee) {
            long long a, b;
            if (g_ei_mode) {
                const long long* p64 = (const long long*)ei_raw;
                a = p64[e];  b = p64[Ee + e];
            } else {
                const int* p32 = (const int*)ei_raw;
                a = p32[e];  b = p32[Ee + e];
            }
            srci = (int)a; if (srci < 0) srci = 0; if (srci >= Nn) srci = Nn - 1;
            dsti = (int)b; if (dsti < 0) dsti = 0; if (dsti >= Nn) dsti = Nn - 1;
            dx = pos[dsti * 3 + 0] - pos[srci * 3 + 0];
            dy = pos[dsti * 3 + 1] - pos[srci * 3 + 1];
            dz = pos[dsti * 3 + 2] - pos[srci * 3 + 2];
            dd = sqrtf(dx * dx + dy * dy + dz * dz);
            inv = (dd > 0.f) ? 1.0f / dd : 0.0f;
        }
        srcsh[tid] = srci;
        dstsh[tid] = dsti;
        dirs[tid * 4 + 0] = dx * inv;
        dirs[tid * 4 + 1] = dy * inv;
        dirs[tid * 4 + 2] = dz * inv;
        dists[tid] = dd;
    }
    __syncthreads();

    // ---- phase 2: build h0 = tf32([s[src] | s[dst] | rbf | 0-pad]) ----
    {
        int rbeg = wid * 8;
#pragma unroll
        for (int rr = 0; rr < 8; rr++) {
            int r = rbeg + rr;
            int srci = srcsh[r], dsti = dstsh[r];
            bool valid = (e0 + r) < Ee;
            float dd = dists[r];
            for (int cc = lane; cc < LD0; cc += 32) {
                float val = 0.0f;
                if (valid) {
                    if (cc < F_DIM) {
                        val = s[(size_t)srci * F_DIM + cc];
                    } else if (cc < 2 * F_DIM) {
                        val = s[(size_t)dsti * F_DIM + (cc - F_DIM)];
                    } else if (cc < IN_DIM) {
                        int k = cc - 2 * F_DIM;
                        float u = (dd - centers[k]) / (widths[k] + 1e-8f);
                        val = __expf(-u * u);
                    }
                }
                h0[r * LD0 + cc] = __uint_as_float(f2tf(val));
            }
        }
    }
    __syncthreads();

    float c[2][8][4];

    // ---- GEMM1: h1 = tf32(silu(h0 @ W1 + b1)) ----
    gemm_mma<NK1>(h0, LD0, g_wpack, c, g, t, lane, warp_m, warp_n);
#pragma unroll
    for (int nt = 0; nt < 8; nt++) {
        int col = warp_n * 64 + nt * 8 + 2 * t;
        float2 bb = *(const float2*)(b1 + col);
#pragma unroll
        for (int mt = 0; mt < 2; mt++) {
            int r0 = warp_m * 32 + mt * 16 + g;
            float2 v0, v1;
            v0.x = __uint_as_float(f2tf(silu_f(c[mt][nt][0] + bb.x)));
            v0.y = __uint_as_float(f2tf(silu_f(c[mt][nt][1] + bb.y)));
            v1.x = __uint_as_float(f2tf(silu_f(c[mt][nt][2] + bb.x)));
            v1.y = __uint_as_float(f2tf(silu_f(c[mt][nt][3] + bb.y)));
            *(float2*)(h1 + r0 * LD1 + col)       = v0;
            *(float2*)(h1 + (r0 + 8) * LD1 + col) = v1;
        }
    }
    __syncthreads();

    // ---- GEMM2: h2 = tf32(silu(h1 @ W2 + b2)), into h0's buffer (stride LD1) ----
    gemm_mma<NK2>(h1, LD1, g_wpack + NK1 * PACK_PER_KS, c, g, t, lane, warp_m, warp_n);
#pragma unroll
    for (int nt = 0; nt < 8; nt++) {
        int col = warp_n * 64 + nt * 8 + 2 * t;
        float2 bb = *(const float2*)(b2 + col);
#pragma unroll
        for (int mt = 0; mt < 2; mt++) {
            int r0 = warp_m * 32 + mt * 16 + g;
            float2 v0, v1;
            v0.x = __uint_as_float(f2tf(silu_f(c[mt][nt][0] + bb.x)));
            v0.y = __uint_as_float(f2tf(silu_f(c[mt][nt][1] + bb.y)));
            v1.x = __uint_as_float(f2tf(silu_f(c[mt][nt][2] + bb.x)));
            v1.y = __uint_as_float(f2tf(silu_f(c[mt][nt][3] + bb.y)));
            *(float2*)(h0 + r0 * LD1 + col)       = v0;
            *(float2*)(h0 + (r0 + 8) * LD1 + col) = v1;
        }
    }
    __syncthreads();

    // ---- GEMM3: [ds | dv_mag] = h2 @ [Ws | Wv]; scatter with red.v2 ----
    gemm_mma<NK3>(h0, LD1, g_wpack + (NK1 + NK2) * PACK_PER_KS, c, g, t, lane, warp_m, warp_n);
    const size_t NF = (size_t)Nn * F_DIM;
    if (warp_n < 2) {
        // ds: output cols 0..127
#pragma unroll
        for (int nt = 0; nt < 8; nt++) {
            int col = warp_n * 64 + nt * 8 + 2 * t;
            float2 bb = *(const float2*)(bs + col);
#pragma unroll
            for (int mt = 0; mt < 2; mt++) {
#pragma unroll
                for (int rg = 0; rg < 2; rg++) {
                    int r = warp_m * 32 + mt * 16 + g + rg * 8;
                    if (e0 + r < Ee) {
                        float* p = out + (size_t)dstsh[r] * F_DIM + col;
                        red2(p, c[mt][nt][2 * rg] + bb.x, c[mt][nt][2 * rg + 1] + bb.y);
                    }
                }
            }
        }
    } else {
        // dv: output cols 128..255 -> magnitude cols 0..127
#pragma unroll
        for (int nt = 0; nt < 8; nt++) {
            int col = (warp_n - 2) * 64 + nt * 8 + 2 * t;
            float2 bb = *(const float2*)(bv + col);
#pragma unroll
            for (int mt = 0; mt < 2; mt++) {
#pragma unroll
                for (int rg = 0; rg < 2; rg++) {
                    int r = warp_m * 32 + mt * 16 + g + rg * 8;
                    if (e0 + r < Ee) {
                        float m0 = c[mt][nt][2 * rg]     + bb.x;
                        float m1 = c[mt][nt][2 * rg + 1] + bb.y;
                        float dx = dirs[r * 4 + 0];
                        float dy = dirs[r * 4 + 1];
                        float dz = dirs[r * 4 + 2];
                        float* base = out + NF + (size_t)dstsh[r] * (3 * F_DIM) + col;
                        red2(base,             dx * m0, dx * m1);
                        red2(base + F_DIM,     dy * m0, dy * m1);
                        red2(base + 2 * F_DIM, dz * m0, dz * m1);
                    }
                }
            }
        }
    }
}

// out[0:N*F] = s ; out[N*F:] = v
__global__ void painn_init_kernel(float4* __restrict__ out,
                                  const float4* __restrict__ s,
                                  const float4* __restrict__ v,
                                  size_t nf4, size_t tot4)
{
    size_t i = (size_t)blockIdx.x * blockDim.x + threadIdx.x;
    if (i >= tot4) return;
    out[i] = (i < nf4) ? s[i] : v[i - nf4];
}

extern "C" void kernel_launch(void* const* d_in, const int* in_sizes, int n_in,
                              void* d_out, int out_size)
{
    const float* s       = (const float*)d_in[0];
    const float* v       = (const float*)d_in[1];
    const float* pos     = (const float*)d_in[2];
    const void*  ei      = (const void*)d_in[3];
    const float* W1      = (const float*)d_in[4];
    const float* b1      = (const float*)d_in[5];
    const float* W2      = (const float*)d_in[6];
    const float* b2      = (const float*)d_in[7];
    const float* Ws      = (const float*)d_in[8];
    const float* bs      = (const float*)d_in[9];
    const float* Wv      = (const float*)d_in[10];
    const float* bv      = (const float*)d_in[11];
    const float* centers = (const float*)d_in[12];
    const float* widths  = (const float*)d_in[13];
    float* out = (float*)d_out;

    const int       Nn = in_sizes[0] / F_DIM;
    const long long Ee = in_sizes[3] / 2;

    // sniff edge_index dtype
    detect_ei_kernel<<<1, 1>>>(ei, Ee, Nn);

    // pack weights into tf32 fragment order (deterministic, every launch)
    {
        const int TOT = (NK1 + NK2 + NK3) * PACK_PER_KS;
        pack_weights_kernel<<<(TOT + 255) / 256, 256>>>(W1, W2, Ws, Wv);
    }

    // init: out = [s ; v]
    size_t nf4  = (size_t)Nn * F_DIM / 4;
    size_t tot4 = (size_t)Nn * F_DIM;       // (F + 3F)/4 floats-per-float4
    painn_init_kernel<<<(int)((tot4 + 255) / 256), 256>>>(
        (float4*)out, (const float4*)s, (const float4*)v, nf4, tot4);

    // fused tf32-mma edge kernel
    size_t smem_bytes =
        (size_t)(TILE * LD0 + TILE * LD1 + TILE * 4 + TILE) * sizeof(float)
        + 2 * TILE * sizeof(int);
    cudaFuncSetAttribute(painn_mma_kernel,
                         cudaFuncAttributeMaxDynamicSharedMemorySize,
                         (int)smem_bytes);
    int blocks = (int)((Ee + TILE - 1) / TILE);
    painn_mma_kernel<<<blocks, NTHREADS, smem_bytes>>>(
        s, pos, ei, b1, b2, bs, bv, centers, widths, out, Nn, Ee);
}

// round 14
// speedup vs baseline: 8.9252x; 1.8673x over previous
#include <cuda_runtime.h>
#include <cuda_fp16.h>

#define F_DIM    128
#define NRBF     20
#define IN_DIM   276           // 2F + NRBF
#define TILE     64            // edges per block
#define NTHREADS 256
#define LDH0     296           // h0 leading dim in halves (148 words, 148%32=20 -> conflict-free)
#define LDH1     264           // h1/h2 leading dim in halves (132 words, 132%32=4 -> conflict-free)
#define NK1      35            // tf32 k8 steps, GEMM1 (K padded 276->280)
#define NK2      32            // GEMM2 K=256
#define NK3      32            // GEMM3 K=256
#define NKT      (NK1 + NK2 + NK3)
#define PACK_PER_KS 2048       // floats per k-step: 32 n-tiles * 32 lanes * 2

// edge_index dtype mode: 1 = int64, 0 = int32 (sniffed at runtime)
__device__ int g_ei_mode;
// fragment-packed tf32 weights: [gemm][ks][nt][lane][2]  (identical to passing round 8)
__device__ float g_wpack[NKT * PACK_PER_KS];

__device__ __forceinline__ unsigned f2tf(float x) {
    unsigned u; asm("cvt.rna.tf32.f32 %0, %1;" : "=r"(u) : "f"(x)); return u;
}
__device__ __forceinline__ float silu_f(float x) { return x / (1.0f + __expf(-x)); }

__device__ __forceinline__ void mma_tf32(float c[4], const unsigned a[4], const unsigned b[2]) {
    asm volatile(
        "mma.sync.aligned.m16n8k8.row.col.f32.tf32.tf32.f32 "
        "{%0,%1,%2,%3}, {%4,%5,%6,%7}, {%8,%9}, {%0,%1,%2,%3};"
        : "+f"(c[0]), "+f"(c[1]), "+f"(c[2]), "+f"(c[3])
        : "r"(a[0]), "r"(a[1]), "r"(a[2]), "r"(a[3]), "r"(b[0]), "r"(b[1]));
}
__device__ __forceinline__ void red2(float* p, float x, float y) {
    asm volatile("red.global.add.v2.f32 [%0], {%1,%2};"
                 :: "l"(p), "f"(x), "f"(y) : "memory");
}

// ---------------- dtype sniffer ----------------
__global__ void detect_ei_kernel(const void* __restrict__ ei, long long Ee, int Nn) {
    const long long* p64 = (const long long*)ei;
    int ok = 1;
    long long ns = (Ee < 64) ? Ee : 64;
    for (long long i = 0; i < ns; i++) {
        long long a = p64[i];
        if (a < 0 || a >= (long long)Nn) { ok = 0; break; }
    }
    g_ei_mode = ok;
}

// ---------------- weight fragment packer (tf32; verbatim round 8) -------------
// pack[gks][nt][lane][j] = tf32(W[8*gks + (lane&3) + 4j][8*nt + (lane>>2)])
__global__ void pack_weights_kernel(const float* __restrict__ W1,
                                    const float* __restrict__ W2,
                                    const float* __restrict__ Ws,
                                    const float* __restrict__ Wv)
{
    int idx = blockIdx.x * blockDim.x + threadIdx.x;
    const int TOT = NKT * PACK_PER_KS;
    if (idx >= TOT) return;
    int j    = idx & 1;
    int lane = (idx >> 1) & 31;
    int nt   = (idx >> 6) & 31;
    int gks  = idx >> 11;
    int g = lane >> 2, t = lane & 3;
    int col = nt * 8 + g;
    int kk  = t + 4 * j;
    float val = 0.0f;
    if (gks < NK1) {
        int k = gks * 8 + kk;
        if (k < IN_DIM) val = W1[k * 256 + col];
    } else if (gks < NK1 + NK2) {
        int k = (gks - NK1) * 8 + kk;
        val = W2[k * 256 + col];
    } else {
        int k = (gks - NK1 - NK2) * 8 + kk;
        val = (col < 128) ? Ws[k * 128 + col] : Wv[k * 128 + (col - 128)];
    }
    g_wpack[idx] = __uint_as_float(f2tf(val));
}

// ---------------- warp-tiled tf32 GEMM: C[64x256] = A[64xK] @ Wpack -----------
// warp tile 32x64. A: __half smem, scalar 16-bit LDS (conflict-free), exact
// half->float conversion feeds the proven tf32 fragment path. B: packed global
// float2 loads, double-buffered.
template<int NK>
__device__ __forceinline__ void gemm_mma(
    const __half* __restrict__ Asm, int LD,        // leading dim in halves
    const float* __restrict__ Wg, float (&c)[2][8][4],
    int g, int t, int lane, int warp_m, int warp_n)
{
#pragma unroll
    for (int mt = 0; mt < 2; mt++)
#pragma unroll
        for (int nt = 0; nt < 8; nt++)
#pragma unroll
            for (int q = 0; q < 4; q++) c[mt][nt][q] = 0.0f;

    const float2* wp = (const float2*)Wg + warp_n * 8 * 32 + lane;
    const __half* ah = Asm + (warp_m * 32 + g) * LD + t;

    unsigned b[2][8][2];
#pragma unroll
    for (int nt = 0; nt < 8; nt++) {
        float2 v = __ldg(wp + nt * 32);
        b[0][nt][0] = __float_as_uint(v.x);
        b[0][nt][1] = __float_as_uint(v.y);
    }

#pragma unroll
    for (int ks = 0; ks < NK; ks++) {
        const int cur = ks & 1, nxt = cur ^ 1;
        if (ks + 1 < NK) {
            const float2* wq = wp + (ks + 1) * 1024;
#pragma unroll
            for (int nt = 0; nt < 8; nt++) {
                float2 v = __ldg(wq + nt * 32);
                b[nxt][nt][0] = __float_as_uint(v.x);
                b[nxt][nt][1] = __float_as_uint(v.y);
            }
        }
        unsigned a[2][4];
        const __half* ap = ah + ks * 8;
#pragma unroll
        for (int mt = 0; mt < 2; mt++) {
            const __half* p = ap + mt * 16 * LD;
            a[mt][0] = __float_as_uint(__half2float(p[0]));
            a[mt][1] = __float_as_uint(__half2float(p[8 * LD]));
            a[mt][2] = __float_as_uint(__half2float(p[4]));
            a[mt][3] = __float_as_uint(__half2float(p[8 * LD + 4]));
        }
#pragma unroll
        for (int mt = 0; mt < 2; mt++)
#pragma unroll
            for (int nt = 0; nt < 8; nt++)
                mma_tf32(c[mt][nt], a[mt], b[cur][nt]);
    }
}

__global__ __launch_bounds__(NTHREADS, 2)
void painn_mma_kernel(
    const float* __restrict__ s, const float* __restrict__ pos,
    const void* __restrict__ ei_raw,
    const float* __restrict__ b1, const float* __restrict__ b2,
    const float* __restrict__ bs, const float* __restrict__ bv,
    const float* __restrict__ centers, const float* __restrict__ widths,
    float* __restrict__ out, int Nn, long long Ee)
{
    extern __shared__ __align__(16) char smraw[];
    __half* h0   = (__half*)smraw;                 // 64*296 halves
    __half* h1   = h0 + TILE * LDH0;               // 64*264 halves
    float* dirs  = (float*)(h1 + TILE * LDH1);     // 64*4
    float* dists = dirs + TILE * 4;                // 64
    int*   srcsh = (int*)(dists + TILE);           // 64
    int*   dstsh = srcsh + TILE;                   // 64

    const int tid  = threadIdx.x;
    const int lane = tid & 31;
    const int wid  = tid >> 5;
    const int g = lane >> 2, t = lane & 3;
    const int warp_n = wid & 3;      // 4 groups of 64 cols
    const int warp_m = wid >> 2;     // 2 groups of 32 rows
    const long long e0 = (long long)blockIdx.x * TILE;

    // ---- phase 1: per-edge geometry ----
    if (tid < TILE) {
        long long e = e0 + tid;
        int srci = 0, dsti = 0;
        float dx = 0.f, dy = 0.f, dz = 0.f, dd = 0.f, inv = 0.f;
        if (e < Ee) {
            long long a, b;
            if (g_ei_mode) {
                const long long* p64 = (const long long*)ei_raw;
                a = p64[e];  b = p64[Ee + e];
            } else {
                const int* p32 = (const int*)ei_raw;
                a = p32[e];  b = p32[Ee + e];
            }
            srci = (int)a; if (srci < 0) srci = 0; if (srci >= Nn) srci = Nn - 1;
            dsti = (int)b; if (dsti < 0) dsti = 0; if (dsti >= Nn) dsti = Nn - 1;
            dx = pos[dsti * 3 + 0] - pos[srci * 3 + 0];
            dy = pos[dsti * 3 + 1] - pos[srci * 3 + 1];
            dz = pos[dsti * 3 + 2] - pos[srci * 3 + 2];
            dd = sqrtf(dx * dx + dy * dy + dz * dz);
            inv = (dd > 0.f) ? 1.0f / dd : 0.0f;
        }
        srcsh[tid] = srci;
        dstsh[tid] = dsti;
        dirs[tid * 4 + 0] = dx * inv;
        dirs[tid * 4 + 1] = dy * inv;
        dirs[tid * 4 + 2] = dz * inv;
        dists[tid] = dd;
    }
    __syncthreads();

    // ---- phase 2: build h0 = f16([s[src] | s[dst] | rbf | 0-pad]) ----
    {
        int rbeg = wid * 8;
#pragma unroll
        for (int rr = 0; rr < 8; rr++) {
            int r = rbeg + rr;
            int srci = srcsh[r], dsti = dstsh[r];
            bool valid = (e0 + r) < Ee;
            float dd = dists[r];
            __half2* row = (__half2*)(h0 + r * LDH0);
            for (int cc = lane; cc < LDH0 / 2; cc += 32) {
                int c0 = 2 * cc;                 // even; never straddles regions
                float v0 = 0.f, v1 = 0.f;
                if (valid) {
                    if (c0 < F_DIM) {
                        const float* p = s + (size_t)srci * F_DIM + c0;
                        v0 = p[0]; v1 = p[1];
                    } else if (c0 < 2 * F_DIM) {
                        const float* p = s + (size_t)dsti * F_DIM + (c0 - F_DIM);
                        v0 = p[0]; v1 = p[1];
                    } else if (c0 < IN_DIM) {
                        int k = c0 - 2 * F_DIM;
                        float u0 = (dd - centers[k]) / (widths[k] + 1e-8f);
                        float u1 = (dd - centers[k + 1]) / (widths[k + 1] + 1e-8f);
                        v0 = __expf(-u0 * u0);
                        v1 = __expf(-u1 * u1);
                    }
                }
                row[cc] = __floats2half2_rn(v0, v1);
            }
        }
    }
    __syncthreads();

    float c[2][8][4];

    // ---- GEMM1: h1 = f16(silu(h0 @ W1 + b1)) ----
    gemm_mma<NK1>(h0, LDH0, g_wpack, c, g, t, lane, warp_m, warp_n);
#pragma unroll
    for (int nt = 0; nt < 8; nt++) {
        int col = warp_n * 64 + nt * 8 + 2 * t;
        float2 bb = *(const float2*)(b1 + col);
#pragma unroll
        for (int mt = 0; mt < 2; mt++) {
            int r0 = warp_m * 32 + mt * 16 + g;
            *(__half2*)(h1 + r0 * LDH1 + col) =
                __floats2half2_rn(silu_f(c[mt][nt][0] + bb.x), silu_f(c[mt][nt][1] + bb.y));
            *(__half2*)(h1 + (r0 + 8) * LDH1 + col) =
                __floats2half2_rn(silu_f(c[mt][nt][2] + bb.x), silu_f(c[mt][nt][3] + bb.y));
        }
    }
    __syncthreads();

    // ---- GEMM2: h2 = f16(silu(h1 @ W2 + b2)), into h0's buffer (stride LDH1) ----
    gemm_mma<NK2>(h1, LDH1, g_wpack + NK1 * PACK_PER_KS, c, g, t, lane, warp_m, warp_n);
#pragma unroll
    for (int nt = 0; nt < 8; nt++) {
        int col = warp_n * 64 + nt * 8 + 2 * t;
        float2 bb = *(const float2*)(b2 + col);
#pragma unroll
        for (int mt = 0; mt < 2; mt++) {
            int r0 = warp_m * 32 + mt * 16 + g;
            *(__half2*)(h0 + r0 * LDH1 + col) =
                __floats2half2_rn(silu_f(c[mt][nt][0] + bb.x), silu_f(c[mt][nt][1] + bb.y));
            *(__half2*)(h0 + (r0 + 8) * LDH1 + col) =
                __floats2half2_rn(silu_f(c[mt][nt][2] + bb.x), silu_f(c[mt][nt][3] + bb.y));
        }
    }
    __syncthreads();

    // ---- GEMM3: [ds | dv_mag] = h2 @ [Ws | Wv]; scatter with red.v2 ----
    gemm_mma<NK3>(h0, LDH1, g_wpack + (NK1 + NK2) * PACK_PER_KS, c, g, t, lane, warp_m, warp_n);
    const size_t NF = (size_t)Nn * F_DIM;
    if (warp_n < 2) {
        // ds: output cols 0..127
#pragma unroll
        for (int nt = 0; nt < 8; nt++) {
            int col = warp_n * 64 + nt * 8 + 2 * t;
            float2 bb = *(const float2*)(bs + col);
#pragma unroll
            for (int mt = 0; mt < 2; mt++) {
#pragma unroll
                for (int rg = 0; rg < 2; rg++) {
                    int r = warp_m * 32 + mt * 16 + g + rg * 8;
                    if (e0 + r < Ee) {
                        float* p = out + (size_t)dstsh[r] * F_DIM + col;
                        red2(p, c[mt][nt][2 * rg] + bb.x, c[mt][nt][2 * rg + 1] + bb.y);
                    }
                }
            }
        }
    } else {
        // dv: magnitude cols 0..127, expanded by direction
#pragma unroll
        for (int nt = 0; nt < 8; nt++) {
            int col = (warp_n - 2) * 64 + nt * 8 + 2 * t;
            float2 bb = *(const float2*)(bv + col);
#pragma unroll
            for (int mt = 0; mt < 2; mt++) {
#pragma unroll
                for (int rg = 0; rg < 2; rg++) {
                    int r = warp_m * 32 + mt * 16 + g + rg * 8;
                    if (e0 + r < Ee) {
                        float m0 = c[mt][nt][2 * rg]     + bb.x;
                        float m1 = c[mt][nt][2 * rg + 1] + bb.y;
                        float dx = dirs[r * 4 + 0];
                        float dy = dirs[r * 4 + 1];
                        float dz = dirs[r * 4 + 2];
                        float* base = out + NF + (size_t)dstsh[r] * (3 * F_DIM) + col;
                        red2(base,             dx * m0, dx * m1);
                        red2(base + F_DIM,     dy * m0, dy * m1);
                        red2(base + 2 * F_DIM, dz * m0, dz * m1);
                    }
                }
            }
        }
    }
}

// out[0:N*F] = s ; out[N*F:] = v
__global__ void painn_init_kernel(float4* __restrict__ out,
                                  const float4* __restrict__ s,
                                  const float4* __restrict__ v,
                                  size_t nf4, size_t tot4)
{
    size_t i = (size_t)blockIdx.x * blockDim.x + threadIdx.x;
    if (i >= tot4) return;
    out[i] = (i < nf4) ? s[i] : v[i - nf4];
}

extern "C" void kernel_launch(void* const* d_in, const int* in_sizes, int n_in,
                              void* d_out, int out_size)
{
    const float* s       = (const float*)d_in[0];
    const float* v       = (const float*)d_in[1];
    const float* pos     = (const float*)d_in[2];
    const void*  ei      = (const void*)d_in[3];
    const float* W1      = (const float*)d_in[4];
    const float* b1      = (const float*)d_in[5];
    const float* W2      = (const float*)d_in[6];
    const float* b2      = (const float*)d_in[7];
    const float* Ws      = (const float*)d_in[8];
    const float* bs      = (const float*)d_in[9];
    const float* Wv      = (const float*)d_in[10];
    const float* bv      = (const float*)d_in[11];
    const float* centers = (const float*)d_in[12];
    const float* widths  = (const float*)d_in[13];
    float* out = (float*)d_out;

    const int       Nn = in_sizes[0] / F_DIM;
    const long long Ee = in_sizes[3] / 2;

    // sniff edge_index dtype
    detect_ei_kernel<<<1, 1>>>(ei, Ee, Nn);

    // pack weights into tf32 fragment order
    pack_weights_kernel<<<(NKT * PACK_PER_KS + 255) / 256, 256>>>(W1, W2, Ws, Wv);

    // init: out = [s ; v]
    size_t nf4  = (size_t)Nn * F_DIM / 4;
    size_t tot4 = (size_t)Nn * F_DIM;       // (F + 3F)/4 floats-per-float4
    painn_init_kernel<<<(int)((tot4 + 255) / 256), 256>>>(
        (float4*)out, (const float4*)s, (const float4*)v, nf4, tot4);

    // fused tf32-mma edge kernel, half-precision activation storage, 2 CTAs/SM
    size_t smem_bytes =
        (size_t)(TILE * LDH0 + TILE * LDH1) * sizeof(__half)
        + (size_t)(TILE * 4 + TILE) * sizeof(float)
        + 2 * TILE * sizeof(int);
    cudaFuncSetAttribute(painn_mma_kernel,
                         cudaFuncAttributeMaxDynamicSharedMemorySize,
                         (int)smem_bytes);
    int blocks = (int)((Ee + TILE - 1) / TILE);
    painn_mma_kernel<<<blocks, NTHREADS, smem_bytes>>>(
        s, pos, ei, b1, b2, bs, bv, centers, widths, out, Nn, Ee);
}